// round 11
// baseline (speedup 1.0000x reference)
#include <cuda_runtime.h>

// TransOp expm: out[b, s*8..] = expm(A_{b,s}) @ x[b, s*8..]
// A_{b,s} = sum_m c[b,m] * psi[m,s,:,:]  (8x8).
//
// BATCH-PACKED f32x2: each f32x2 holds {problem b0, problem b1}. A thread
// pair (h=0,1) handles two problems jointly; thread h owns rows 4h..4h+3 of
// both A matrices (32 ull). Multipliers {v_b0[k], v_b1[k]} are naturally
// packed -> pure-FFMA2 inner loop. Partner half of v via 4x 64-bit shfl.xor.
// Each 8-term dot product is split into two independent 4-chains (own cols /
// partner cols) so the partner chain overlaps the SHFL latency; combined
// with one add2.
//
// Occupancy: BDIM=128, launch_bounds(128,5) -> target <=102 regs, 5 CTAs/SM
// (640 threads/SM, 8 warps/SMSP). The A-build loads c in 4-wide chunks to
// keep peak register pressure under the cap.
//
// Taylor action, warp-uniform (order m, reps r) from warp-max ||A||_inf:
//   <=2.6: m=10  <=3.6: m=12  <=4.8: m=14  <=6.0: m=16  <=7.2: m=19
//   else: r = ceil(wmax/3.2), m=13, A scaled by 1/r.
// Horner: v = b; for j=m..1: v = b + (A v)/j.

typedef unsigned long long ull;

#define BDIM 128

__constant__ float2 INV2[32] = {
    {0.0f,0.0f},       {1.0f,1.0f},       {1.0f/2,1.0f/2},   {1.0f/3,1.0f/3},
    {1.0f/4,1.0f/4},   {1.0f/5,1.0f/5},   {1.0f/6,1.0f/6},   {1.0f/7,1.0f/7},
    {1.0f/8,1.0f/8},   {1.0f/9,1.0f/9},   {1.0f/10,1.0f/10}, {1.0f/11,1.0f/11},
    {1.0f/12,1.0f/12}, {1.0f/13,1.0f/13}, {1.0f/14,1.0f/14}, {1.0f/15,1.0f/15},
    {1.0f/16,1.0f/16}, {1.0f/17,1.0f/17}, {1.0f/18,1.0f/18}, {1.0f/19,1.0f/19},
    {1.0f/20,1.0f/20}, {1.0f/21,1.0f/21}, {1.0f/22,1.0f/22}, {1.0f/23,1.0f/23},
    {1.0f/24,1.0f/24}, {1.0f/25,1.0f/25}, {1.0f/26,1.0f/26}, {1.0f/27,1.0f/27},
    {1.0f/28,1.0f/28}, {1.0f/29,1.0f/29}, {1.0f/30,1.0f/30}, {1.0f/31,1.0f/31}
};

__device__ __forceinline__ ull dup2(float v) {
    ull r; asm("mov.b64 %0, {%1,%1};" : "=l"(r) : "f"(v)); return r;
}
__device__ __forceinline__ ull pack2(float lo, float hi) {
    ull r; asm("mov.b64 %0, {%1,%2};" : "=l"(r) : "f"(lo), "f"(hi)); return r;
}
__device__ __forceinline__ void unpack2(ull v, float& lo, float& hi) {
    asm("mov.b64 {%0,%1}, %2;" : "=f"(lo), "=f"(hi) : "l"(v));
}
__device__ __forceinline__ ull fma2(ull a, ull b, ull c) {
    ull d; asm("fma.rn.f32x2 %0, %1, %2, %3;" : "=l"(d) : "l"(a), "l"(b), "l"(c)); return d;
}
__device__ __forceinline__ ull mul2(ull a, ull b) {
    ull d; asm("mul.rn.f32x2 %0, %1, %2;" : "=l"(d) : "l"(a), "l"(b)); return d;
}
__device__ __forceinline__ ull add2(ull a, ull b) {
    ull d; asm("add.rn.f32x2 %0, %1, %2;" : "=l"(d) : "l"(a), "l"(b)); return d;
}

__global__ __launch_bounds__(BDIM, 5) void transop_expm_kernel(
    const float* __restrict__ x,
    const float* __restrict__ c,
    const float* __restrict__ psi,
    float* __restrict__ out)
{
    // psi slice for this CTA's s, each scalar duplicated into both f32x2
    // lanes so the batch-packed A build is straight LDS + FFMA2.
    __shared__ ull psd[16][64];          // 8 KB, [m][row*8+col]

    const int s = blockIdx.x & 63;
    const int t = threadIdx.x;
    const int h = t & 1;                 // row-half owner within the pair
    const int p = t >> 1;                // pair index 0..63
    const int b0 = (blockIdx.x >> 6) * BDIM + 2 * p;   // 128 problems / CTA
    const int b1 = b0 + 1;

    // Stage psi (duplicated): 128 threads x 8 floats (2x float4) each.
    {
        const int m = t >> 3;            // 0..15
        const int j = (t & 7) << 3;      // 0,8,...,56 : linear row*8+col
        const float* src = psi + ((m * 64 + s) << 6) + j;
        const float4 v0 = *reinterpret_cast<const float4*>(src);
        const float4 v1 = *reinterpret_cast<const float4*>(src + 4);
        psd[m][j + 0] = dup2(v0.x);
        psd[m][j + 1] = dup2(v0.y);
        psd[m][j + 2] = dup2(v0.z);
        psd[m][j + 3] = dup2(v0.w);
        psd[m][j + 4] = dup2(v1.x);
        psd[m][j + 5] = dup2(v1.y);
        psd[m][j + 6] = dup2(v1.z);
        psd[m][j + 7] = dup2(v1.w);
    }
    __syncthreads();

    // Batch-packed A build for rows 4h..4h+3 of both problems.
    // Storage: A2[r*8+q] = A[4h+r][(q+4h)&7]  (own columns first).
    // Own group (q=0..3):     base p0 = row 4h, col 4h      (contiguous)
    // Partner group (q=4..7): base p1 = row 4h, col 4-4h    (contiguous)
    const ulonglong2* q0 = reinterpret_cast<const ulonglong2*>(
        &psd[0][0] + 36 * h);            // 32h (row) + 4h (col)
    const ulonglong2* q1 = reinterpret_cast<const ulonglong2*>(
        &psd[0][0] + 28 * h + 4);        // 32h (row) + 4-4h (col)

    const float4* c0p = reinterpret_cast<const float4*>(c + b0 * 16);
    const float4* c1p = reinterpret_cast<const float4*>(c + b1 * 16);

    ull A2[32];
    // c loaded in 4-wide chunks to cap register pressure during the build.
#pragma unroll
    for (int mc = 0; mc < 4; ++mc) {
        const float4 ca = c0p[mc];
        const float4 cbq = c1p[mc];
        ull cch[4];
        cch[0] = pack2(ca.x, cbq.x);
        cch[1] = pack2(ca.y, cbq.y);
        cch[2] = pack2(ca.z, cbq.z);
        cch[3] = pack2(ca.w, cbq.w);
#pragma unroll
        for (int mm = 0; mm < 4; ++mm) {
            const int m = mc * 4 + mm;
            const ull cd = cch[mm];
#pragma unroll
            for (int r = 0; r < 4; ++r) {
                const ulonglong2 oa = q0[m * 32 + r * 4 + 0];   // own q=0,1
                const ulonglong2 ob = q0[m * 32 + r * 4 + 1];   // own q=2,3
                const ulonglong2 pa = q1[m * 32 + r * 4 + 0];   // part q=4,5
                const ulonglong2 pb = q1[m * 32 + r * 4 + 1];   // part q=6,7
                if (m == 0) {
                    A2[r * 8 + 0] = mul2(cd, oa.x);
                    A2[r * 8 + 1] = mul2(cd, oa.y);
                    A2[r * 8 + 2] = mul2(cd, ob.x);
                    A2[r * 8 + 3] = mul2(cd, ob.y);
                    A2[r * 8 + 4] = mul2(cd, pa.x);
                    A2[r * 8 + 5] = mul2(cd, pa.y);
                    A2[r * 8 + 6] = mul2(cd, pb.x);
                    A2[r * 8 + 7] = mul2(cd, pb.y);
                } else {
                    A2[r * 8 + 0] = fma2(cd, oa.x, A2[r * 8 + 0]);
                    A2[r * 8 + 1] = fma2(cd, oa.y, A2[r * 8 + 1]);
                    A2[r * 8 + 2] = fma2(cd, ob.x, A2[r * 8 + 2]);
                    A2[r * 8 + 3] = fma2(cd, ob.y, A2[r * 8 + 3]);
                    A2[r * 8 + 4] = fma2(cd, pa.x, A2[r * 8 + 4]);
                    A2[r * 8 + 5] = fma2(cd, pa.y, A2[r * 8 + 5]);
                    A2[r * 8 + 6] = fma2(cd, pb.x, A2[r * 8 + 6]);
                    A2[r * 8 + 7] = fma2(cd, pb.y, A2[r * 8 + 7]);
                }
            }
        }
    }

    // Infinity norm over this thread's 4 rows of BOTH problems (column
    // permutation does not change row sums). Warp reduce -> uniform tier.
    float ninf = 0.0f;
    {
        const ull mask = 0x7FFFFFFF7FFFFFFFULL;
#pragma unroll
        for (int r = 0; r < 4; ++r) {
            ull acc = A2[r * 8] & mask;
#pragma unroll
            for (int k = 1; k < 8; ++k) acc = add2(acc, A2[r * 8 + k] & mask);
            float a0, a1; unpack2(acc, a0, a1);
            ninf = fmaxf(ninf, fmaxf(a0, a1));
        }
    }
    const float wmax = __uint_as_float(
        __reduce_max_sync(0xffffffffu, __float_as_uint(ninf)));

    int m_ord, r;
    if (wmax <= 2.6f)       { m_ord = 10; r = 1; }
    else if (wmax <= 3.6f)  { m_ord = 12; r = 1; }
    else if (wmax <= 4.8f)  { m_ord = 14; r = 1; }
    else if (wmax <= 6.0f)  { m_ord = 16; r = 1; }
    else if (wmax <= 7.2f)  { m_ord = 19; r = 1; }
    else {
        r = (int)ceilf(wmax * (1.0f / 3.2f));
        if (r > 31) r = 31;
        m_ord = 13;
    }

    if (r > 1) {
        const ull s2 = *reinterpret_cast<const ull*>(&INV2[r]);
#pragma unroll
        for (int i = 0; i < 32; ++i) A2[i] = mul2(A2[i], s2);
    }

    // Own 4 elements (global rows 4h..4h+3) of x for both problems, packed.
    ull v2[4];
    {
        const float4 xa = *reinterpret_cast<const float4*>(x + b0 * 512 + s * 8 + 4 * h);
        const float4 xb = *reinterpret_cast<const float4*>(x + b1 * 512 + s * 8 + 4 * h);
        v2[0] = pack2(xa.x, xb.x);
        v2[1] = pack2(xa.y, xb.y);
        v2[2] = pack2(xa.z, xb.z);
        v2[3] = pack2(xa.w, xb.w);
    }

    // r repetitions of order-m Horner Taylor action. Pure FFMA2 inner loop,
    // own/partner 4-chains overlapped with the SHFL exchange.
    for (int rr = 0; rr < r; ++rr) {
        const ull b2_0 = v2[0], b2_1 = v2[1], b2_2 = v2[2], b2_3 = v2[3];
        for (int j = m_ord; j > 0; --j) {
            // Partner half of v (its own-ordered 4 ull) — in flight while the
            // own-column chains below execute.
            const ull q0v = __shfl_xor_sync(0xffffffffu, v2[0], 1);
            const ull q1v = __shfl_xor_sync(0xffffffffu, v2[1], 1);
            const ull q2v = __shfl_xor_sync(0xffffffffu, v2[2], 1);
            const ull q3v = __shfl_xor_sync(0xffffffffu, v2[3], 1);

            // Own-column chains (depth 4, ILP 4) — no SHFL dependence.
            ull u0 = mul2(A2[0],  v2[0]);
            ull u1 = mul2(A2[8],  v2[0]);
            ull u2 = mul2(A2[16], v2[0]);
            ull u3 = mul2(A2[24], v2[0]);
#pragma unroll
            for (int k = 1; k < 4; ++k) {
                u0 = fma2(A2[0  + k], v2[k], u0);
                u1 = fma2(A2[8  + k], v2[k], u1);
                u2 = fma2(A2[16 + k], v2[k], u2);
                u3 = fma2(A2[24 + k], v2[k], u3);
            }
            // Partner-column chains (depth 4, ILP 4).
            ull p0 = mul2(A2[4],  q0v);
            ull p1 = mul2(A2[12], q0v);
            ull p2 = mul2(A2[20], q0v);
            ull p3 = mul2(A2[28], q0v);
            p0 = fma2(A2[5],  q1v, p0); p0 = fma2(A2[6],  q2v, p0);
            p0 = fma2(A2[7],  q3v, p0);
            p1 = fma2(A2[13], q1v, p1); p1 = fma2(A2[14], q2v, p1);
            p1 = fma2(A2[15], q3v, p1);
            p2 = fma2(A2[21], q1v, p2); p2 = fma2(A2[22], q2v, p2);
            p2 = fma2(A2[23], q3v, p2);
            p3 = fma2(A2[29], q1v, p3); p3 = fma2(A2[30], q2v, p3);
            p3 = fma2(A2[31], q3v, p3);

            const ull sj = *reinterpret_cast<const ull*>(&INV2[j]);
            v2[0] = fma2(add2(u0, p0), sj, b2_0);
            v2[1] = fma2(add2(u1, p1), sj, b2_1);
            v2[2] = fma2(add2(u2, p2), sj, b2_2);
            v2[3] = fma2(add2(u3, p3), sj, b2_3);
        }
    }

    // Store: each ull splits into one element of b0's row and one of b1's.
    {
        float lo, hi;
        float* o0 = out + b0 * 512 + s * 8 + 4 * h;
        float* o1 = out + b1 * 512 + s * 8 + 4 * h;
        unpack2(v2[0], lo, hi); o0[0] = lo; o1[0] = hi;
        unpack2(v2[1], lo, hi); o0[1] = lo; o1[1] = hi;
        unpack2(v2[2], lo, hi); o0[2] = lo; o1[2] = hi;
        unpack2(v2[3], lo, hi); o0[3] = lo; o1[3] = hi;
    }
}

extern "C" void kernel_launch(void* const* d_in, const int* in_sizes, int n_in,
                              void* d_out, int out_size)
{
    const float* x   = (const float*)d_in[0];   // (B, 512)
    const float* c   = (const float*)d_in[1];   // (B, 16)
    const float* psi = (const float*)d_in[2];   // (16, 64, 8, 8)
    float* out = (float*)d_out;                 // (B, 512)

    const int B = in_sizes[0] / 512;            // 8192
    // Each CTA: one s, 128 problems (64 thread pairs x 2 batch-packed).
    const dim3 grid((B / BDIM) * 64);           // 4096 CTAs
    transop_expm_kernel<<<grid, BDIM>>>(x, c, psi, out);
}

// round 15
// speedup vs baseline: 1.4098x; 1.4098x over previous
#include <cuda_runtime.h>
#include <cstdint>

// TransOp expm: out[b, s*8..] = expm(A_{b,s}) @ x[b, s*8..]
// A_{b,s} = sum_m c[b,m] * psi[m,s,:,:]  (8x8). Thread = problem.
//
// smem: psi slice pre-paired row-wise (NOT duplicated):
//   ps2[m][i*8+k] = { psi[m,s,2i,k], psi[m,s,2i+1,k] }   (4 KB)
// A-build: A2[j] (row-pair packed) accumulated with FFMA2 from warp-uniform
// LDS.128 reads (2 ull per load, broadcast across the warp) and a per-m
// dup2(c[m]) multiplier. 8 LDS.128 + 16 FFMA2 per m.
//
// Taylor action, warp-uniform (order m, reps r) from warp-max ||A||_inf:
//   <=2.6: m=9  <=3.6: m=11  <=4.8: m=13  <=6.0: m=15  <=7.2: m=18
//   else: r = ceil(wmax/3.2), m=13, A scaled by 1/r.
// Horner: v = b; for j=m..1: v = b + (A v)/j.   All heavy FP is FFMA2.

typedef unsigned long long ull;

#define BDIM 128

__constant__ float2 INV2[32] = {
    {0.0f,0.0f},       {1.0f,1.0f},       {1.0f/2,1.0f/2},   {1.0f/3,1.0f/3},
    {1.0f/4,1.0f/4},   {1.0f/5,1.0f/5},   {1.0f/6,1.0f/6},   {1.0f/7,1.0f/7},
    {1.0f/8,1.0f/8},   {1.0f/9,1.0f/9},   {1.0f/10,1.0f/10}, {1.0f/11,1.0f/11},
    {1.0f/12,1.0f/12}, {1.0f/13,1.0f/13}, {1.0f/14,1.0f/14}, {1.0f/15,1.0f/15},
    {1.0f/16,1.0f/16}, {1.0f/17,1.0f/17}, {1.0f/18,1.0f/18}, {1.0f/19,1.0f/19},
    {1.0f/20,1.0f/20}, {1.0f/21,1.0f/21}, {1.0f/22,1.0f/22}, {1.0f/23,1.0f/23},
    {1.0f/24,1.0f/24}, {1.0f/25,1.0f/25}, {1.0f/26,1.0f/26}, {1.0f/27,1.0f/27},
    {1.0f/28,1.0f/28}, {1.0f/29,1.0f/29}, {1.0f/30,1.0f/30}, {1.0f/31,1.0f/31}
};

__device__ __forceinline__ ull dup2(float v) {
    ull r; asm("mov.b64 %0, {%1,%1};" : "=l"(r) : "f"(v)); return r;
}
__device__ __forceinline__ ull pack2(float lo, float hi) {
    ull r; asm("mov.b64 %0, {%1,%2};" : "=l"(r) : "f"(lo), "f"(hi)); return r;
}
__device__ __forceinline__ void unpack2(ull v, float& lo, float& hi) {
    asm("mov.b64 {%0,%1}, %2;" : "=f"(lo), "=f"(hi) : "l"(v));
}
__device__ __forceinline__ ull fma2(ull a, ull b, ull c) {
    ull d; asm("fma.rn.f32x2 %0, %1, %2, %3;" : "=l"(d) : "l"(a), "l"(b), "l"(c)); return d;
}
__device__ __forceinline__ ull mul2(ull a, ull b) {
    ull d; asm("mul.rn.f32x2 %0, %1, %2;" : "=l"(d) : "l"(a), "l"(b)); return d;
}
__device__ __forceinline__ ull add2(ull a, ull b) {
    ull d; asm("add.rn.f32x2 %0, %1, %2;" : "=l"(d) : "l"(a), "l"(b)); return d;
}

__global__ __launch_bounds__(BDIM, 4) void transop_expm_kernel(
    const float* __restrict__ x,
    const float* __restrict__ c,
    const float* __restrict__ psi,
    float* __restrict__ out)
{
    // Row-paired psi slice for this CTA's s (4 KB, not duplicated).
    __shared__ ull ps2[16][32];

    const int s = blockIdx.x & 63;
    const int t = threadIdx.x;
    const int b = (blockIdx.x >> 6) * BDIM + t;   // thread = problem

    // Stage: 128 threads; thread covers (m = t>>3, i2 = (t&7)>>1, k0 = (t&1)*4).
    // Loads rows 2*i2 and 2*i2+1, cols k0..k0+3; packs 4 ull.
    {
        const int m  = t >> 3;
        const int q  = t & 7;
        const int i2 = q >> 1;
        const int k0 = (q & 1) << 2;
        const float* src = psi + ((m * 64 + s) << 6) + i2 * 16 + k0;
        const float4 r0 = *reinterpret_cast<const float4*>(src);       // row 2i2
        const float4 r1 = *reinterpret_cast<const float4*>(src + 8);   // row 2i2+1
        ps2[m][i2 * 8 + k0 + 0] = pack2(r0.x, r1.x);
        ps2[m][i2 * 8 + k0 + 1] = pack2(r0.y, r1.y);
        ps2[m][i2 * 8 + k0 + 2] = pack2(r0.z, r1.z);
        ps2[m][i2 * 8 + k0 + 3] = pack2(r0.w, r1.w);
    }
    __syncthreads();

    // A-build: A2[j] = {A[2i][k], A[2i+1][k]}, j = i*8+k. LDS.128 (2 ull) per
    // access, warp-uniform addresses -> broadcast wavefronts.
    const ulonglong2* pp = reinterpret_cast<const ulonglong2*>(&ps2[0][0]);
    const float4* cr = reinterpret_cast<const float4*>(c + (size_t)b * 16);

    ull A2[32];
#pragma unroll
    for (int mc = 0; mc < 4; ++mc) {           // c in 4-wide chunks (reg cap)
        const float4 cv = cr[mc];
        const float cf[4] = {cv.x, cv.y, cv.z, cv.w};
#pragma unroll
        for (int mm = 0; mm < 4; ++mm) {
            const int m = mc * 4 + mm;
            const ull cd = dup2(cf[mm]);
#pragma unroll
            for (int u = 0; u < 16; ++u) {
                const ulonglong2 z = pp[m * 16 + u];
                if (m == 0) {
                    A2[2 * u + 0] = mul2(cd, z.x);
                    A2[2 * u + 1] = mul2(cd, z.y);
                } else {
                    A2[2 * u + 0] = fma2(cd, z.x, A2[2 * u + 0]);
                    A2[2 * u + 1] = fma2(cd, z.y, A2[2 * u + 1]);
                }
            }
        }
    }

    // Infinity norm (packed abs row sums) -> warp-uniform tier.
    float ninf = 0.0f;
    {
        const ull mask = 0x7FFFFFFF7FFFFFFFULL;
#pragma unroll
        for (int i = 0; i < 4; ++i) {
            ull acc = A2[i * 8] & mask;
#pragma unroll
            for (int k = 1; k < 8; ++k) acc = add2(acc, A2[i * 8 + k] & mask);
            float a0, a1; unpack2(acc, a0, a1);
            ninf = fmaxf(ninf, fmaxf(a0, a1));
        }
    }
    const float wmax = __uint_as_float(
        __reduce_max_sync(0xffffffffu, __float_as_uint(ninf)));

    int m_ord, reps;
    if (wmax <= 2.6f)       { m_ord = 9;  reps = 1; }
    else if (wmax <= 3.6f)  { m_ord = 11; reps = 1; }
    else if (wmax <= 4.8f)  { m_ord = 13; reps = 1; }
    else if (wmax <= 6.0f)  { m_ord = 15; reps = 1; }
    else if (wmax <= 7.2f)  { m_ord = 18; reps = 1; }
    else {
        reps = (int)ceilf(wmax * (1.0f / 3.2f));
        if (reps > 31) reps = 31;
        m_ord = 13;
    }

    if (reps > 1) {
        const ull s2 = *reinterpret_cast<const ull*>(&INV2[reps]);
#pragma unroll
        for (int i = 0; i < 32; ++i) A2[i] = mul2(A2[i], s2);
    }

    // x block: natural element pairs match the row-pair packing.
    ull v2[4];
    {
        const float4 xa = *reinterpret_cast<const float4*>(x + (size_t)b * 512 + s * 8);
        const float4 xb = *reinterpret_cast<const float4*>(x + (size_t)b * 512 + s * 8 + 4);
        v2[0] = pack2(xa.x, xa.y);
        v2[1] = pack2(xa.z, xa.w);
        v2[2] = pack2(xb.x, xb.y);
        v2[3] = pack2(xb.z, xb.w);
    }

    // reps repetitions of order-m Horner Taylor action. Pure FFMA2 + 8 dup/step.
    for (int rr = 0; rr < reps; ++rr) {
        const ull b2_0 = v2[0], b2_1 = v2[1], b2_2 = v2[2], b2_3 = v2[3];
        for (int j = m_ord; j > 0; --j) {
            float vf[8];
            unpack2(v2[0], vf[0], vf[1]);
            unpack2(v2[1], vf[2], vf[3]);
            unpack2(v2[2], vf[4], vf[5]);
            unpack2(v2[3], vf[6], vf[7]);
            ull dm[8];
#pragma unroll
            for (int k = 0; k < 8; ++k) dm[k] = dup2(vf[k]);

            ull w0 = mul2(A2[0],  dm[0]);
            ull w1 = mul2(A2[8],  dm[0]);
            ull w2 = mul2(A2[16], dm[0]);
            ull w3 = mul2(A2[24], dm[0]);
#pragma unroll
            for (int k = 1; k < 8; ++k) {
                w0 = fma2(A2[0  + k], dm[k], w0);
                w1 = fma2(A2[8  + k], dm[k], w1);
                w2 = fma2(A2[16 + k], dm[k], w2);
                w3 = fma2(A2[24 + k], dm[k], w3);
            }

            const ull sj = *reinterpret_cast<const ull*>(&INV2[j]);
            v2[0] = fma2(w0, sj, b2_0);
            v2[1] = fma2(w1, sj, b2_1);
            v2[2] = fma2(w2, sj, b2_2);
            v2[3] = fma2(w3, sj, b2_3);
        }
    }

    // Store 8 outputs (two STG.128).
    {
        float y0, y1, y2, y3, y4, y5, y6, y7;
        unpack2(v2[0], y0, y1);
        unpack2(v2[1], y2, y3);
        unpack2(v2[2], y4, y5);
        unpack2(v2[3], y6, y7);
        float4* ob = reinterpret_cast<float4*>(out + (size_t)b * 512 + s * 8);
        ob[0] = make_float4(y0, y1, y2, y3);
        ob[1] = make_float4(y4, y5, y6, y7);
    }
}

extern "C" void kernel_launch(void* const* d_in, const int* in_sizes, int n_in,
                              void* d_out, int out_size)
{
    const float* x   = (const float*)d_in[0];   // (B, 512)
    const float* c   = (const float*)d_in[1];   // (B, 16)
    const float* psi = (const float*)d_in[2];   // (16, 64, 8, 8)
    float* out = (float*)d_out;                 // (B, 512)

    const int B = in_sizes[0] / 512;            // 8192
    // Each CTA: one s, 128 problems (thread = problem).
    const dim3 grid((B / BDIM) * 64);           // 4096 CTAs
    transop_expm_kernel<<<grid, BDIM>>>(x, c, psi, out);
}